// round 11
// baseline (speedup 1.0000x reference)
#include <cuda_runtime.h>
#include <math.h>

// Problem dims (fixed)
#define B_   128
#define T_   500
#define NI_  256
#define N_   256
#define M_   (B_*T_)
#define TBN_ ((size_t)T_*B_*N_)

// xw scratch, m-pair interleaved: ULL index p*256+n holds (xw[2p][n], xw[2p+1][n])
__device__ unsigned long long g_xw[(size_t)M_ * N_ / 2];

// Packed fp32x2 helpers
#define FFMA2(d, a, b, c) \
    asm("fma.rn.f32x2 %0, %1, %2, %3;" : "=l"(d) : "l"(a), "l"(b), "l"(c))
#define PACK2(d, s) \
    asm("mov.b64 %0, {%1, %1};" : "=l"(d) : "f"(s))
#define PACKAB(d, lo, hi) \
    asm("mov.b64 %0, {%1, %2};" : "=l"(d) : "f"(lo), "f"(hi))

// ===========================================================================
// Kernel 1: xw = x @ w_in. BM=128, BN=128, BK=16, 256 thr, 8m x 8n microtile.
// 2 CTAs/SM, classic grid (R6 version — best measured ~155us).
// ===========================================================================
#define ASTRIDE 132
#define ASZ (2*16*ASTRIDE)
#define BSZ (2*16*128)
#define GEMM_SMEM ((ASZ + BSZ) * 4)

__global__ void __launch_bounds__(256, 2)
gemm_xw(const float* __restrict__ A, const float* __restrict__ W)
{
    extern __shared__ float gsm[];
    float* As = gsm;
    float* Bs = gsm + ASZ;

    const int t   = threadIdx.x;
    const int bm  = blockIdx.x << 7;
    const int bn0 = blockIdx.y << 7;
    const int tn  = t & 15;
    const int m0  = (t >> 4) << 3;

    const int amr[2] = { (t) >> 2, (t + 256) >> 2 };
    const int akc    = (t & 3) << 2;
    const int bkr[2] = { t >> 5, (t + 256) >> 5 };
    const int bnc    = (t & 31) << 2;

    unsigned long long acc[4][8];
#pragma unroll
    for (int e = 0; e < 4; e++)
#pragma unroll
        for (int j = 0; j < 8; j++) acc[e][j] = 0ull;

    float4 ra[2];

#pragma unroll
    for (int i = 0; i < 2; i++)
        ra[i] = *(const float4*)(A + (size_t)(bm + amr[i]) * NI_ + akc);
#pragma unroll
    for (int i = 0; i < 2; i++) {
        unsigned dst = (unsigned)__cvta_generic_to_shared(Bs + bkr[i] * 128 + bnc);
        asm volatile("cp.async.cg.shared.global [%0], [%1], 16;"
                     :: "r"(dst), "l"(W + (size_t)bkr[i] * N_ + bn0 + bnc));
    }
    asm volatile("cp.async.commit_group;");
#pragma unroll
    for (int i = 0; i < 2; i++) {
        As[(akc + 0) * ASTRIDE + amr[i]] = ra[i].x;
        As[(akc + 1) * ASTRIDE + amr[i]] = ra[i].y;
        As[(akc + 2) * ASTRIDE + amr[i]] = ra[i].z;
        As[(akc + 3) * ASTRIDE + amr[i]] = ra[i].w;
    }
    asm volatile("cp.async.wait_group 0;");
    __syncthreads();

    for (int kt = 0; kt < 16; kt++) {
        const int st = kt & 1;
        if (kt < 15) {
#pragma unroll
            for (int i = 0; i < 2; i++)
                ra[i] = *(const float4*)(A + (size_t)(bm + amr[i]) * NI_
                                           + (kt + 1) * 16 + akc);
#pragma unroll
            for (int i = 0; i < 2; i++) {
                unsigned dst = (unsigned)__cvta_generic_to_shared(
                    Bs + (st ^ 1) * (16 * 128) + bkr[i] * 128 + bnc);
                asm volatile("cp.async.cg.shared.global [%0], [%1], 16;"
                    :: "r"(dst),
                       "l"(W + (size_t)((kt+1)*16 + bkr[i]) * N_ + bn0 + bnc));
            }
            asm volatile("cp.async.commit_group;");
        }

        const float* as = As + st * (16 * ASTRIDE);
        const float* bs = Bs + st * (16 * 128);
#pragma unroll
        for (int k = 0; k < 16; k++) {
            ulonglong2 aA = *(const ulonglong2*)(as + k * ASTRIDE + m0);
            ulonglong2 aB = *(const ulonglong2*)(as + k * ASTRIDE + m0 + 4);
            unsigned long long am4[4] = { aA.x, aA.y, aB.x, aB.y };
            float4 bv0 = *(const float4*)(bs + k * 128 + (tn << 2));
            float4 bv1 = *(const float4*)(bs + k * 128 + 64 + (tn << 2));
            unsigned long long b[8];
            PACK2(b[0], bv0.x); PACK2(b[1], bv0.y);
            PACK2(b[2], bv0.z); PACK2(b[3], bv0.w);
            PACK2(b[4], bv1.x); PACK2(b[5], bv1.y);
            PACK2(b[6], bv1.z); PACK2(b[7], bv1.w);
#pragma unroll
            for (int e = 0; e < 4; e++)
#pragma unroll
                for (int j = 0; j < 8; j++)
                    FFMA2(acc[e][j], am4[e], b[j], acc[e][j]);
        }
        if (kt == 15) break;

#pragma unroll
        for (int i = 0; i < 2; i++) {
            float* ad = As + (st ^ 1) * (16 * ASTRIDE);
            ad[(akc + 0) * ASTRIDE + amr[i]] = ra[i].x;
            ad[(akc + 1) * ASTRIDE + amr[i]] = ra[i].y;
            ad[(akc + 2) * ASTRIDE + amr[i]] = ra[i].z;
            ad[(akc + 3) * ASTRIDE + amr[i]] = ra[i].w;
        }
        asm volatile("cp.async.wait_group 0;");
        __syncthreads();
    }

    unsigned long long* op = g_xw;
    const int pbase = (bm + m0) >> 1;
#pragma unroll
    for (int e = 0; e < 4; e++) {
        size_t prow = (size_t)(pbase + e) * 256 + bn0;
        ulonglong2 s0, s1, s2, s3;
        s0.x = acc[e][0]; s0.y = acc[e][1];
        s1.x = acc[e][2]; s1.y = acc[e][3];
        s2.x = acc[e][4]; s2.y = acc[e][5];
        s3.x = acc[e][6]; s3.y = acc[e][7];
        *(ulonglong2*)(op + prow + (tn << 2))          = s0;
        *(ulonglong2*)(op + prow + (tn << 2) + 2)      = s1;
        *(ulonglong2*)(op + prow + 64 + (tn << 2))     = s2;
        *(ulonglong2*)(op + prow + 64 + (tn << 2) + 2) = s3;
    }
}

// ===========================================================================
// Kernel 2: LSNN scan — R6 structure with critical-path cuts:
//  - new_a/thr/base/nonref/lsd+1 precomputed during gather-load latency
//  - new_v = fma(omdv, i_in, base): 1 FLOP after the sum tree
//  - dense high-row dot split into 4 accumulator chains
// ===========================================================================
#define WROWS 222
#define SENT  (222 << 10)
#define LCAP  232
#define OFF_FLAT (223*256)
#define OFF_CNT  (OFF_FLAT + 2*LCAP)
#define OFF_TOT  (OFF_CNT + 16)
#define OFF_ZHI  (OFF_TOT + 4)
#define SCAN_SMEM ((OFF_ZHI + 2*36) * 4)    // 230608 B

__global__ void __launch_bounds__(256, 1)
lsnn_scan(const float* __restrict__ w_rec,
          const float* __restrict__ z0,  const float* __restrict__ v0,
          const float* __restrict__ a0,  const float* __restrict__ lsd0,
          float* __restrict__ out, float decay_v, float decay_a)
{
    extern __shared__ float sm[];
    float* w_sm  = sm;                       // [223][256], row 222 = zeros
    int*   flatL = (int*)(sm + OFF_FLAT);    // [2][232]
    int*   cntS  = (int*)(sm + OFF_CNT);     // [2][8]
    int*   totS  = (int*)(sm + OFF_TOT);     // [2]
    float* zhi   = sm + OFF_ZHI;             // [2][36]

    const int b    = blockIdx.x;
    const int n    = threadIdx.x;
    const int w    = n >> 5;
    const int lane = n & 31;

    {
        const float4* src = (const float4*)w_rec;
        float4*       dst = (float4*)w_sm;
        for (int i = n; i < WROWS * 64; i += 256) dst[i] = src[i];
    }
    unsigned long long wp[17];
#pragma unroll
    for (int j = 0; j < 17; j++) {
        float wlo = w_rec[(size_t)(222 + 2*j) * 256 + n];
        float whi = w_rec[(size_t)(223 + 2*j) * 256 + n];
        if (n == 222 + 2*j) wlo = 0.f;
        if (n == 223 + 2*j) whi = 0.f;
        PACKAB(wp[j], wlo, whi);
    }
    w_sm[WROWS * 256 + n] = 0.f;
    if (n < 16) cntS[n] = 0;
    if (n < 2)  totS[n] = 0;
    if (n < 72) zhi[n] = 0.f;
    __syncthreads();
    if (n < WROWS) w_sm[n * 256 + n] = 0.f;

    float z_self = z0[b * N_ + n];
    float v      = v0[b * N_ + n];
    float a      = a0[b * N_ + n];
    float lsd    = lsd0[b * N_ + n];

    {
        unsigned m    = __ballot_sync(0xffffffffu, z_self != 0.f);
        unsigned mseg = (w == 6) ? (m & 0x3FFFFFFFu) : m;
        if (w < 7) { if (lane == 0) cntS[w] = __popc(mseg); }
        if (n >= 222) zhi[n - 222] = z_self;
        __syncthreads();
        int4 cA = *(const int4*)&cntS[0];
        int4 cB = *(const int4*)&cntS[4];
        if (w < 7) {
            int start = 0;
            if (w > 0) start += cA.x; if (w > 1) start += cA.y;
            if (w > 2) start += cA.z; if (w > 3) start += cA.w;
            if (w > 4) start += cB.x; if (w > 5) start += cB.y;
            if ((mseg >> lane) & 1u) {
                int r = __popc(mseg & ((1u << lane) - 1u));
                flatL[start + r] = n << 10;
            }
        }
        if (w == 7) {
            int tt = cA.x + cA.y + cA.z + cA.w + cB.x + cB.y + cB.z;
            if (lane < 8 || tt + lane < 32) flatL[tt + lane] = SENT;
            if (lane == 0) totS[0] = tt;
        }
    }

    const float omdv = 1.f - decay_v;
    const float omda = 1.f - decay_a;
    const char*  wpn = (const char*)w_sm + (n << 2);
    const float* xwb = (const float*)g_xw;
    const int    mb0 = b * T_;
    const int    twon = n << 1;

#define XW_LD(tt_) __ldcs(xwb + (((size_t)((mb0 + (tt_)) >> 1)) << 9) + twon + ((mb0 + (tt_)) & 1))
    float xw_c  = XW_LD(0);
    float xw_n1 = XW_LD(1);
    __syncthreads();

#pragma unroll 1
    for (int t = 0; t < T_; t++) {
        const int rb = t & 1, wb = rb ^ 1;

        float xw_n2 = (t + 2 < T_) ? XW_LD(t + 2) : 0.f;

        const int  tot = totS[rb];
        const int* fl  = flatL + rb * LCAP;
        const unsigned long long* zp =
            (const unsigned long long*)(zhi + rb * 36);

        const int4* fc = (const int4*)fl;
        int4 c0 = fc[0], c1 = fc[1], c2 = fc[2], c3 = fc[3];
        int4 c4 = fc[4], c5 = fc[5], c6 = fc[6], c7 = fc[7];

        // ---- precompute next-state terms that don't depend on i_in ----
        // (fills gather-load latency; collapses post-gather chain to 1 FMA)
        float new_a  = __fadd_rn(__fmul_rn(decay_a, a), __fmul_rn(omda, z_self));
        float thr    = __fadd_rn(0.03f, __fmul_rn(new_a, 1.8f));
        float base   = __fadd_rn(__fmul_rn(decay_v, v), __fmul_rn(-thr, z_self));
        int   nonref = (lsd >= 2.f);
        float lsp1   = __fadd_rn(lsd, 1.f);

        float av[8];
#pragma unroll
        for (int j = 0; j < 8; j++) av[j] = 0.f;

        // dense high-row dot, 4 accumulator chains
        unsigned long long h0, h1, h2, h3;
        PACKAB(h0, 0.f, 0.f); PACKAB(h1, 0.f, 0.f);
        PACKAB(h2, 0.f, 0.f); PACKAB(h3, 0.f, 0.f);
#pragma unroll
        for (int j = 0; j < 16; j += 4) {
            FFMA2(h0, zp[j],   wp[j],   h0);
            FFMA2(h1, zp[j+1], wp[j+1], h1);
            FFMA2(h2, zp[j+2], wp[j+2], h2);
            FFMA2(h3, zp[j+3], wp[j+3], h3);
        }
        FFMA2(h0, zp[16], wp[16], h0);

        av[0] += *(const float*)(wpn + c0.x);
        av[1] += *(const float*)(wpn + c0.y);
        av[2] += *(const float*)(wpn + c0.z);
        av[3] += *(const float*)(wpn + c0.w);
        av[4] += *(const float*)(wpn + c1.x);
        av[5] += *(const float*)(wpn + c1.y);
        av[6] += *(const float*)(wpn + c1.z);
        av[7] += *(const float*)(wpn + c1.w);
        av[0] += *(const float*)(wpn + c2.x);
        av[1] += *(const float*)(wpn + c2.y);
        av[2] += *(const float*)(wpn + c2.z);
        av[3] += *(const float*)(wpn + c2.w);
        av[4] += *(const float*)(wpn + c3.x);
        av[5] += *(const float*)(wpn + c3.y);
        av[6] += *(const float*)(wpn + c3.z);
        av[7] += *(const float*)(wpn + c3.w);
        av[0] += *(const float*)(wpn + c4.x);
        av[1] += *(const float*)(wpn + c4.y);
        av[2] += *(const float*)(wpn + c4.z);
        av[3] += *(const float*)(wpn + c4.w);
        av[4] += *(const float*)(wpn + c5.x);
        av[5] += *(const float*)(wpn + c5.y);
        av[6] += *(const float*)(wpn + c5.z);
        av[7] += *(const float*)(wpn + c5.w);
        av[0] += *(const float*)(wpn + c6.x);
        av[1] += *(const float*)(wpn + c6.y);
        av[2] += *(const float*)(wpn + c6.z);
        av[3] += *(const float*)(wpn + c6.w);
        av[4] += *(const float*)(wpn + c7.x);
        av[5] += *(const float*)(wpn + c7.y);
        av[6] += *(const float*)(wpn + c7.z);
        av[7] += *(const float*)(wpn + c7.w);

#pragma unroll 1
        for (int j = 32; j < tot; j += 4) {
            int4 o = *(const int4*)(fl + j);
            av[0] += *(const float*)(wpn + o.x);
            av[1] += *(const float*)(wpn + o.y);
            av[2] += *(const float*)(wpn + o.z);
            av[3] += *(const float*)(wpn + o.w);
        }

        // combine: dense pairs + gather tree + xw
        float2 f0 = *(float2*)&h0, f1 = *(float2*)&h1;
        float2 f2 = *(float2*)&h2, f3 = *(float2*)&h3;
        float hd = __fadd_rn(__fadd_rn(__fadd_rn(f0.x, f0.y), __fadd_rn(f1.x, f1.y)),
                             __fadd_rn(__fadd_rn(f2.x, f2.y), __fadd_rn(f3.x, f3.y)));
        const float i_in = __fadd_rn(__fadd_rn(xw_c, hd),
            __fadd_rn(__fadd_rn(__fadd_rn(av[0], av[1]), __fadd_rn(av[2], av[3])),
                      __fadd_rn(__fadd_rn(av[4], av[5]), __fadd_rn(av[6], av[7]))));

        // 1 FMA + compare on the critical path
        float new_v = __fmaf_rn(omdv, i_in, base);
        int   spk   = (new_v > thr) && nonref;

        unsigned m    = __ballot_sync(0xffffffffu, spk);
        unsigned mseg = (w == 6) ? (m & 0x3FFFFFFFu) : m;
        if (w < 7) { if (lane == 0) cntS[wb * 8 + w] = __popc(mseg); }

        float zf = spk ? 1.f : 0.f;
        if (n >= 222) zhi[wb * 36 + (n - 222)] = zf;

        float new_lsd = __fmul_rn(lsp1, __fadd_rn(1.f, -zf));
        float v_sc    = __fdividef(__fadd_rn(new_v, -thr), thr);
        __syncthreads();

        const size_t ob = ((size_t)t * B_ + b) * N_ + n;
        __stcs(out + ob,            zf);
        __stcs(out + TBN_ + ob,     new_v);
        __stcs(out + 2 * TBN_ + ob, thr);
        __stcs(out + 3 * TBN_ + ob, v_sc);

        {
            int4 cA = *(const int4*)&cntS[wb * 8];
            int4 cB = *(const int4*)&cntS[wb * 8 + 4];
            if (w < 7) {
                int start = 0;
                if (w > 0) start += cA.x; if (w > 1) start += cA.y;
                if (w > 2) start += cA.z; if (w > 3) start += cA.w;
                if (w > 4) start += cB.x; if (w > 5) start += cB.y;
                if ((mseg >> lane) & 1u) {
                    int r = __popc(mseg & ((1u << lane) - 1u));
                    flatL[wb * LCAP + start + r] = n << 10;
                }
            } else {
                int tt = cA.x + cA.y + cA.z + cA.w + cB.x + cB.y + cB.z;
                if (lane < 8 || tt + lane < 32)
                    flatL[wb * LCAP + tt + lane] = SENT;
                if (lane == 0) totS[wb] = tt;
            }
        }

        z_self = zf; v = new_v; a = new_a; lsd = new_lsd;
        xw_c = xw_n1; xw_n1 = xw_n2;
        __syncthreads();
    }
#undef XW_LD
}

// ---------------------------------------------------------------------------
// Launcher (graph-capturable)
// ---------------------------------------------------------------------------
extern "C" void kernel_launch(void* const* d_in, const int* in_sizes, int n_in,
                              void* d_out, int out_size)
{
    const float* x     = (const float*)d_in[0];
    const float* w_in  = (const float*)d_in[1];
    const float* w_rec = (const float*)d_in[2];
    const float* z0    = (const float*)d_in[3];
    const float* v0    = (const float*)d_in[4];
    const float* a0    = (const float*)d_in[5];
    const float* lsd0  = (const float*)d_in[6];
    float* out = (float*)d_out;

    const float decay_v = expf(-1.0f / 20.0f);
    const float decay_a = expf(-1.0f / 20.0f);

    cudaFuncSetAttribute(gemm_xw,
                         cudaFuncAttributeMaxDynamicSharedMemorySize, GEMM_SMEM);
    cudaFuncSetAttribute(lsnn_scan,
                         cudaFuncAttributeMaxDynamicSharedMemorySize, SCAN_SMEM);

    dim3 g1(M_ / 128, 2);
    gemm_xw<<<g1, 256, GEMM_SMEM>>>(x, w_in);
    lsnn_scan<<<B_, 256, SCAN_SMEM>>>(w_rec, z0, v0, a0, lsd0, out,
                                      decay_v, decay_a);
}

// round 13
// speedup vs baseline: 1.0312x; 1.0312x over previous
#include <cuda_runtime.h>
#include <math.h>

// Problem dims (fixed)
#define B_   128
#define T_   500
#define NI_  256
#define N_   256
#define M_   (B_*T_)
#define TBN_ ((size_t)T_*B_*N_)

// xw scratch, m-pair interleaved: ULL index p*256+n holds (xw[2p][n], xw[2p+1][n])
__device__ unsigned long long g_xw[(size_t)M_ * N_ / 2];

// Packed fp32x2 helpers
#define FFMA2(d, a, b, c) \
    asm("fma.rn.f32x2 %0, %1, %2, %3;" : "=l"(d) : "l"(a), "l"(b), "l"(c))
#define PACK2(d, s) \
    asm("mov.b64 %0, {%1, %1};" : "=l"(d) : "f"(s))
#define PACKAB(d, lo, hi) \
    asm("mov.b64 %0, {%1, %2};" : "=l"(d) : "f"(lo), "f"(hi))

// ===========================================================================
// Kernel 1: xw = x @ w_in. BM=128, BN=128, BK=16, 256 thr, 8m x 8n microtile.
// 2 CTAs/SM, classic grid (R6 version — best measured ~155us). UNCHANGED.
// ===========================================================================
#define ASTRIDE 132
#define ASZ (2*16*ASTRIDE)
#define BSZ (2*16*128)
#define GEMM_SMEM ((ASZ + BSZ) * 4)

__global__ void __launch_bounds__(256, 2)
gemm_xw(const float* __restrict__ A, const float* __restrict__ W)
{
    extern __shared__ float gsm[];
    float* As = gsm;
    float* Bs = gsm + ASZ;

    const int t   = threadIdx.x;
    const int bm  = blockIdx.x << 7;
    const int bn0 = blockIdx.y << 7;
    const int tn  = t & 15;
    const int m0  = (t >> 4) << 3;

    const int amr[2] = { (t) >> 2, (t + 256) >> 2 };
    const int akc    = (t & 3) << 2;
    const int bkr[2] = { t >> 5, (t + 256) >> 5 };
    const int bnc    = (t & 31) << 2;

    unsigned long long acc[4][8];
#pragma unroll
    for (int e = 0; e < 4; e++)
#pragma unroll
        for (int j = 0; j < 8; j++) acc[e][j] = 0ull;

    float4 ra[2];

#pragma unroll
    for (int i = 0; i < 2; i++)
        ra[i] = *(const float4*)(A + (size_t)(bm + amr[i]) * NI_ + akc);
#pragma unroll
    for (int i = 0; i < 2; i++) {
        unsigned dst = (unsigned)__cvta_generic_to_shared(Bs + bkr[i] * 128 + bnc);
        asm volatile("cp.async.cg.shared.global [%0], [%1], 16;"
                     :: "r"(dst), "l"(W + (size_t)bkr[i] * N_ + bn0 + bnc));
    }
    asm volatile("cp.async.commit_group;");
#pragma unroll
    for (int i = 0; i < 2; i++) {
        As[(akc + 0) * ASTRIDE + amr[i]] = ra[i].x;
        As[(akc + 1) * ASTRIDE + amr[i]] = ra[i].y;
        As[(akc + 2) * ASTRIDE + amr[i]] = ra[i].z;
        As[(akc + 3) * ASTRIDE + amr[i]] = ra[i].w;
    }
    asm volatile("cp.async.wait_group 0;");
    __syncthreads();

    for (int kt = 0; kt < 16; kt++) {
        const int st = kt & 1;
        if (kt < 15) {
#pragma unroll
            for (int i = 0; i < 2; i++)
                ra[i] = *(const float4*)(A + (size_t)(bm + amr[i]) * NI_
                                           + (kt + 1) * 16 + akc);
#pragma unroll
            for (int i = 0; i < 2; i++) {
                unsigned dst = (unsigned)__cvta_generic_to_shared(
                    Bs + (st ^ 1) * (16 * 128) + bkr[i] * 128 + bnc);
                asm volatile("cp.async.cg.shared.global [%0], [%1], 16;"
                    :: "r"(dst),
                       "l"(W + (size_t)((kt+1)*16 + bkr[i]) * N_ + bn0 + bnc));
            }
            asm volatile("cp.async.commit_group;");
        }

        const float* as = As + st * (16 * ASTRIDE);
        const float* bs = Bs + st * (16 * 128);
#pragma unroll
        for (int k = 0; k < 16; k++) {
            ulonglong2 aA = *(const ulonglong2*)(as + k * ASTRIDE + m0);
            ulonglong2 aB = *(const ulonglong2*)(as + k * ASTRIDE + m0 + 4);
            unsigned long long am4[4] = { aA.x, aA.y, aB.x, aB.y };
            float4 bv0 = *(const float4*)(bs + k * 128 + (tn << 2));
            float4 bv1 = *(const float4*)(bs + k * 128 + 64 + (tn << 2));
            unsigned long long b[8];
            PACK2(b[0], bv0.x); PACK2(b[1], bv0.y);
            PACK2(b[2], bv0.z); PACK2(b[3], bv0.w);
            PACK2(b[4], bv1.x); PACK2(b[5], bv1.y);
            PACK2(b[6], bv1.z); PACK2(b[7], bv1.w);
#pragma unroll
            for (int e = 0; e < 4; e++)
#pragma unroll
                for (int j = 0; j < 8; j++)
                    FFMA2(acc[e][j], am4[e], b[j], acc[e][j]);
        }
        if (kt == 15) break;

#pragma unroll
        for (int i = 0; i < 2; i++) {
            float* ad = As + (st ^ 1) * (16 * ASTRIDE);
            ad[(akc + 0) * ASTRIDE + amr[i]] = ra[i].x;
            ad[(akc + 1) * ASTRIDE + amr[i]] = ra[i].y;
            ad[(akc + 2) * ASTRIDE + amr[i]] = ra[i].z;
            ad[(akc + 3) * ASTRIDE + amr[i]] = ra[i].w;
        }
        asm volatile("cp.async.wait_group 0;");
        __syncthreads();
    }

    unsigned long long* op = g_xw;
    const int pbase = (bm + m0) >> 1;
#pragma unroll
    for (int e = 0; e < 4; e++) {
        size_t prow = (size_t)(pbase + e) * 256 + bn0;
        ulonglong2 s0, s1, s2, s3;
        s0.x = acc[e][0]; s0.y = acc[e][1];
        s1.x = acc[e][2]; s1.y = acc[e][3];
        s2.x = acc[e][4]; s2.y = acc[e][5];
        s3.x = acc[e][6]; s3.y = acc[e][7];
        *(ulonglong2*)(op + prow + (tn << 2))          = s0;
        *(ulonglong2*)(op + prow + (tn << 2) + 2)      = s1;
        *(ulonglong2*)(op + prow + 64 + (tn << 2))     = s2;
        *(ulonglong2*)(op + prow + 64 + (tn << 2) + 2) = s3;
    }
}

// ===========================================================================
// Kernel 2: LSNN scan — ONE barrier per step.
//  - Fixed per-warp segments (warp w owns rows [32w,32w+32), seg cap 36):
//    each warp writes its own spikes right after its ballot — no cross-warp
//    prefix, no second barrier. Double-buffered segments/counts/zhi.
//  - Gather: chunk0 of all 7 segments unconditionally (28 loads, sentinel-
//    padded), rare per-segment tails for overflow chunks.
//  - Rows 222..255 dense via zhi staging + packed reg weights (R6 trick).
//  - Dynamics terms precomputed during gather latency (R10 trick).
// ===========================================================================
#define WROWS 222
#define SENT  (222 << 10)
#define SEGSZ 36
// float offsets
#define OFF_SEG (223*256)                 // segL [2][7][36] ints = 504
#define OFF_CNT (OFF_SEG + 504)           // c4S  [2][8] ints = 16
#define OFF_ZHI (OFF_CNT + 16)            // zhi  [2][36] floats = 72
#define SCAN_SMEM ((OFF_ZHI + 72) * 4)    // 230,720 B

__global__ void __launch_bounds__(256, 1)
lsnn_scan(const float* __restrict__ w_rec,
          const float* __restrict__ z0,  const float* __restrict__ v0,
          const float* __restrict__ a0,  const float* __restrict__ lsd0,
          float* __restrict__ out, float decay_v, float decay_a)
{
    extern __shared__ float sm[];
    float* w_sm = sm;                      // [223][256], row 222 = zeros
    int*   segL = (int*)(sm + OFF_SEG);    // [2][7][36]
    int*   c4S  = (int*)(sm + OFF_CNT);    // [2][8]
    float* zhi  = sm + OFF_ZHI;            // [2][36]

    const int b    = blockIdx.x;
    const int n    = threadIdx.x;
    const int w    = n >> 5;
    const int lane = n & 31;

    // weights rows 0..221 -> smem
    {
        const float4* src = (const float4*)w_rec;
        float4*       dst = (float4*)w_sm;
        for (int i = n; i < WROWS * 64; i += 256) dst[i] = src[i];
    }
    // rows 222..255 -> packed register pairs (17 x f32x2), diag masked
    unsigned long long wp[17];
#pragma unroll
    for (int j = 0; j < 17; j++) {
        float wlo = w_rec[(size_t)(222 + 2*j) * 256 + n];
        float whi = w_rec[(size_t)(223 + 2*j) * 256 + n];
        if (n == 222 + 2*j) wlo = 0.f;
        if (n == 223 + 2*j) whi = 0.f;
        PACKAB(wp[j], wlo, whi);
    }
    w_sm[WROWS * 256 + n] = 0.f;           // zero sentinel row
    if (n < 16) c4S[n] = 0;
    if (n < 72) zhi[n] = 0.f;
    __syncthreads();
    if (n < WROWS) w_sm[n * 256 + n] = 0.f; // diag mask

    float z_self = z0[b * N_ + n];
    float v      = v0[b * N_ + n];
    float a      = a0[b * N_ + n];
    float lsd    = lsd0[b * N_ + n];

    // ---- initial build (buffer 0) — per-warp segments, no prefix ----
    {
        unsigned m = __ballot_sync(0xffffffffu, z_self != 0.f);
        if (w < 7) {
            unsigned mseg = (w == 6) ? (m & 0x3FFFFFFFu) : m;
            int cnt = __popc(mseg);
            int* segw = segL + w * SEGSZ;
            if ((mseg >> lane) & 1u) {
                int r = __popc(mseg & ((1u << lane) - 1u));
                segw[r] = n << 10;
            }
            int padEnd = (cnt + 3) & ~3;
            if (padEnd == 0) padEnd = 4;
            if (lane >= cnt && lane < padEnd) segw[lane] = SENT;
            if (lane == 0) c4S[w] = padEnd >> 2;
        }
        if (n >= 222) zhi[n - 222] = z_self;
    }

    const float omdv = 1.f - decay_v;
    const float omda = 1.f - decay_a;
    const char*  wpn = (const char*)w_sm + (n << 2);
    const float* xwb = (const float*)g_xw;
    const int    mb0 = b * T_;
    const int    twon = n << 1;

#define XW_LD(tt_) __ldcs(xwb + (((size_t)((mb0 + (tt_)) >> 1)) << 9) + twon + ((mb0 + (tt_)) & 1))
    float xw_c  = XW_LD(0);
    float xw_n1 = XW_LD(1);
    __syncthreads();

#pragma unroll 1
    for (int t = 0; t < T_; t++) {
        const int rb = t & 1, wb = rb ^ 1;

        float xw_n2 = (t + 2 < T_) ? XW_LD(t + 2) : 0.f;

        const int* segR = segL + rb * 252;
        // chunk counts for segs 0..6
        int4 ka = *(const int4*)&c4S[rb * 8];
        int4 kb = *(const int4*)&c4S[rb * 8 + 4];
        const unsigned long long* zp =
            (const unsigned long long*)(zhi + rb * 36);

        // unconditional chunk0 of each segment
        int4 s0 = *(const int4*)(segR + 0*SEGSZ);
        int4 s1 = *(const int4*)(segR + 1*SEGSZ);
        int4 s2 = *(const int4*)(segR + 2*SEGSZ);
        int4 s3 = *(const int4*)(segR + 3*SEGSZ);
        int4 s4 = *(const int4*)(segR + 4*SEGSZ);
        int4 s5 = *(const int4*)(segR + 5*SEGSZ);
        int4 s6 = *(const int4*)(segR + 6*SEGSZ);

        // precompute next-state terms independent of i_in
        float new_a  = __fadd_rn(__fmul_rn(decay_a, a), __fmul_rn(omda, z_self));
        float thr    = __fadd_rn(0.03f, __fmul_rn(new_a, 1.8f));
        float base   = __fadd_rn(__fmul_rn(decay_v, v), __fmul_rn(-thr, z_self));
        int   nonref = (lsd >= 2.f);
        float lsp1   = __fadd_rn(lsd, 1.f);

        // dense high-row dot (rows 222..255), 4 chains
        unsigned long long h0, h1, h2, h3;
        PACKAB(h0, 0.f, 0.f); PACKAB(h1, 0.f, 0.f);
        PACKAB(h2, 0.f, 0.f); PACKAB(h3, 0.f, 0.f);
#pragma unroll
        for (int j = 0; j < 16; j += 4) {
            FFMA2(h0, zp[j],   wp[j],   h0);
            FFMA2(h1, zp[j+1], wp[j+1], h1);
            FFMA2(h2, zp[j+2], wp[j+2], h2);
            FFMA2(h3, zp[j+3], wp[j+3], h3);
        }
        FFMA2(h0, zp[16], wp[16], h0);

        float av[8];
#pragma unroll
        for (int j = 0; j < 8; j++) av[j] = 0.f;

        // 28 independent weight loads (sentinels add exact 0)
        av[0] += *(const float*)(wpn + s0.x);
        av[1] += *(const float*)(wpn + s0.y);
        av[2] += *(const float*)(wpn + s0.z);
        av[3] += *(const float*)(wpn + s0.w);
        av[4] += *(const float*)(wpn + s1.x);
        av[5] += *(const float*)(wpn + s1.y);
        av[6] += *(const float*)(wpn + s1.z);
        av[7] += *(const float*)(wpn + s1.w);
        av[0] += *(const float*)(wpn + s2.x);
        av[1] += *(const float*)(wpn + s2.y);
        av[2] += *(const float*)(wpn + s2.z);
        av[3] += *(const float*)(wpn + s2.w);
        av[4] += *(const float*)(wpn + s3.x);
        av[5] += *(const float*)(wpn + s3.y);
        av[6] += *(const float*)(wpn + s3.z);
        av[7] += *(const float*)(wpn + s3.w);
        av[0] += *(const float*)(wpn + s4.x);
        av[1] += *(const float*)(wpn + s4.y);
        av[2] += *(const float*)(wpn + s4.z);
        av[3] += *(const float*)(wpn + s4.w);
        av[4] += *(const float*)(wpn + s5.x);
        av[5] += *(const float*)(wpn + s5.y);
        av[6] += *(const float*)(wpn + s5.z);
        av[7] += *(const float*)(wpn + s5.w);
        av[0] += *(const float*)(wpn + s6.x);
        av[1] += *(const float*)(wpn + s6.y);
        av[2] += *(const float*)(wpn + s6.z);
        av[3] += *(const float*)(wpn + s6.w);

        // per-segment overflow tails (chunks 1..c4-1), usually empty
#define TAIL(segidx, c4v) do {                                        \
        const int* sp_ = segR + (segidx) * SEGSZ;                     \
        _Pragma("unroll 1")                                           \
        for (int j_ = 4; j_ < ((c4v) << 2); j_ += 4) {                \
            int4 o_ = *(const int4*)(sp_ + j_);                       \
            av[4] += *(const float*)(wpn + o_.x);                     \
            av[5] += *(const float*)(wpn + o_.y);                     \
            av[6] += *(const float*)(wpn + o_.z);                     \
            av[7] += *(const float*)(wpn + o_.w);                     \
        } } while (0)
        TAIL(0, ka.x);
        TAIL(1, ka.y);
        TAIL(2, ka.z);
        TAIL(3, ka.w);
        TAIL(4, kb.x);
        TAIL(5, kb.y);
        TAIL(6, kb.z);
#undef TAIL

        // combine
        float2 f0 = *(float2*)&h0, f1 = *(float2*)&h1;
        float2 f2 = *(float2*)&h2, f3 = *(float2*)&h3;
        float hd = __fadd_rn(__fadd_rn(__fadd_rn(f0.x, f0.y), __fadd_rn(f1.x, f1.y)),
                             __fadd_rn(__fadd_rn(f2.x, f2.y), __fadd_rn(f3.x, f3.y)));
        const float i_in = __fadd_rn(__fadd_rn(xw_c, hd),
            __fadd_rn(__fadd_rn(__fadd_rn(av[0], av[1]), __fadd_rn(av[2], av[3])),
                      __fadd_rn(__fadd_rn(av[4], av[5]), __fadd_rn(av[6], av[7]))));

        // 1 FMA + compare on the critical path
        float new_v = __fmaf_rn(omdv, i_in, base);
        int   spk   = (new_v > thr) && nonref;
        float zf    = spk ? 1.f : 0.f;

        // ---- publish next step's state: per-warp segment write (no prefix) ----
        unsigned m = __ballot_sync(0xffffffffu, spk);
        if (w < 7) {
            unsigned mseg = (w == 6) ? (m & 0x3FFFFFFFu) : m;
            int cnt = __popc(mseg);
            int* segw = segL + wb * 252 + w * SEGSZ;
            if ((mseg >> lane) & 1u) {
                int r = __popc(mseg & ((1u << lane) - 1u));
                segw[r] = n << 10;
            }
            int padEnd = (cnt + 3) & ~3;
            if (padEnd == 0) padEnd = 4;
            if (lane >= cnt && lane < padEnd) segw[lane] = SENT;
            if (lane == 0) c4S[wb * 8 + w] = padEnd >> 2;
        }
        if (n >= 222) zhi[wb * 36 + (n - 222)] = zf;

        // epilogue (off recurrence path)
        float new_lsd = __fmul_rn(lsp1, __fadd_rn(1.f, -zf));
        float v_sc    = __fdividef(__fadd_rn(new_v, -thr), thr);

        const size_t ob = ((size_t)t * B_ + b) * N_ + n;
        __stcs(out + ob,            zf);
        __stcs(out + TBN_ + ob,     new_v);
        __stcs(out + 2 * TBN_ + ob, thr);
        __stcs(out + 3 * TBN_ + ob, v_sc);

        z_self = zf; v = new_v; a = new_a; lsd = new_lsd;
        xw_c = xw_n1; xw_n1 = xw_n2;

        __syncthreads();    // the ONE barrier per step
    }
#undef XW_LD
}

// ---------------------------------------------------------------------------
// Launcher (graph-capturable)
// ---------------------------------------------------------------------------
extern "C" void kernel_launch(void* const* d_in, const int* in_sizes, int n_in,
                              void* d_out, int out_size)
{
    const float* x     = (const float*)d_in[0];
    const float* w_in  = (const float*)d_in[1];
    const float* w_rec = (const float*)d_in[2];
    const float* z0    = (const float*)d_in[3];
    const float* v0    = (const float*)d_in[4];
    const float* a0    = (const float*)d_in[5];
    const float* lsd0  = (const float*)d_in[6];
    float* out = (float*)d_out;

    const float decay_v = expf(-1.0f / 20.0f);
    const float decay_a = expf(-1.0f / 20.0f);

    cudaFuncSetAttribute(gemm_xw,
                         cudaFuncAttributeMaxDynamicSharedMemorySize, GEMM_SMEM);
    cudaFuncSetAttribute(lsnn_scan,
                         cudaFuncAttributeMaxDynamicSharedMemorySize, SCAN_SMEM);

    dim3 g1(M_ / 128, 2);
    gemm_xw<<<g1, 256, GEMM_SMEM>>>(x, w_in);
    lsnn_scan<<<B_, 256, SCAN_SMEM>>>(w_rec, z0, v0, a0, lsd0, out,
                                      decay_v, decay_a);
}